// round 17
// baseline (speedup 1.0000x reference)
#include <cuda_runtime.h>
#include <math.h>

#define T_TOK 512
#define CHUNK 64
#define NCHUNK 8
#define HH 28
#define WW 28
#define CC 4
#define DM 3136
#define DH 512

#define FSEG 98    // dadh split-K segments (k = 32 each)
#define PSEG 16    // pred split-K segments (k = 32 each)
#define H0SEG 14   // H0 split-K segments (k = 224 = 7x32 each)

typedef unsigned long long ull;

// ---------------- f32x2 helpers ----------------
__device__ __forceinline__ ull pk2(float lo, float hi) {
    ull r; asm("mov.b64 %0, {%1,%2};" : "=l"(r) : "f"(lo), "f"(hi)); return r;
}
__device__ __forceinline__ void upk2(float& lo, float& hi, ull v) {
    asm("mov.b64 {%0,%1}, %2;" : "=f"(lo), "=f"(hi) : "l"(v));
}
#define FFMA2(d, a, b) asm("fma.rn.f32x2 %0, %1, %2, %0;" : "+l"(d) : "l"(a), "l"(b))
#define ADDX2(d, a)    asm("add.rn.f32x2 %0, %0, %1;" : "+l"(d) : "l"(a))

// ---------------- device scratch ----------------
__device__ __align__(16) float g_nk[T_TOK * DM];
__device__ __align__(16) float g_nv[T_TOK * DM];
__device__ __align__(16) float g_W2[DH * DM];
__device__ __align__(16) float g_b2[DM];
__device__ __align__(16) float g_H0[T_TOK * DH];            // K @ W1_0 + b1_0 (all tokens)
__device__ __align__(16) float g_Hbuf[2][CHUNK * DH];       // H_c ping-pong
__device__ __align__(16) float g_A[2 * CHUNK * DH];         // rows 0-63: A_c ; rows 64-127: A2_{c-1}
__device__ __align__(16) float g_dpred[CHUNK * DM];
__device__ __align__(16) float g_dhist[NCHUNK * CHUNK * DH];// dh history
__device__ __align__(16) float g_Gall[36 * CHUNK * CHUNK];  // G'_{c,c'} = K_c K_{c'}^T + 1 (c' <= c)
__device__ __align__(16) float g_fpart[FSEG * CHUNK * DH];  // dadh partials (12.8 MB)
__device__ __align__(16) float g_ppart[PSEG * 2 * CHUNK * DM]; // pred partials (25.7 MB) / H0 scratch

// ---------------- math helpers ----------------
__device__ __forceinline__ float gelu_f(float x) {
    const float c = 0.7978845608028654f, a = 0.044715f;
    float u = c * (x + a * x * x * x);
    return 0.5f * x * (1.0f + tanhf(u));
}
__device__ __forceinline__ float dgelu_f(float x) {
    const float c = 0.7978845608028654f, a = 0.044715f;
    float x2 = x * x;
    float u = c * (x + a * x * x2);
    float th = tanhf(u);
    return 0.5f * (1.0f + th) + 0.5f * x * (1.0f - th * th) * c * (1.0f + 3.0f * a * x2);
}

// ---------------- prologue: conv3x3+rmsnorm and W2/b2 copy ----------------
__global__ void prologue_kernel(const float* __restrict__ x,
                                const float* __restrict__ wk, const float* __restrict__ bk,
                                const float* __restrict__ wv, const float* __restrict__ bv,
                                const float* __restrict__ sk, const float* __restrict__ sv,
                                const float* __restrict__ W2, const float* __restrict__ b2) {
    int tid = threadIdx.x;
    if (blockIdx.x < 1568) {
        __shared__ float swk[144], swv[144], sbk[4], sbv[4], ssk[4], ssv[4];
        if (tid < 144) { swk[tid] = wk[tid]; swv[tid] = wv[tid]; }
        if (tid < 4) { sbk[tid] = bk[tid]; sbv[tid] = bv[tid]; ssk[tid] = sk[tid]; ssv[tid] = sv[tid]; }
        __syncthreads();
        int idx = blockIdx.x * 256 + tid;   // 401408 exact
        int w = idx % WW;
        int h = (idx / WW) % HH;
        int t = idx / (HH * WW);
        float acck[4], accv[4];
#pragma unroll
        for (int o = 0; o < 4; o++) { acck[o] = sbk[o]; accv[o] = sbv[o]; }
        const float* xt = x + t * (CC * HH * WW);
#pragma unroll
        for (int kh = 0; kh < 3; kh++) {
            int hy = h + kh - 1;
            if (hy < 0 || hy >= HH) continue;
#pragma unroll
            for (int kw = 0; kw < 3; kw++) {
                int wx = w + kw - 1;
                if (wx < 0 || wx >= WW) continue;
                int wbase = (kh * 3 + kw) * 16;
#pragma unroll
                for (int ci = 0; ci < 4; ci++) {
                    float xv = xt[ci * (HH * WW) + hy * WW + wx];
#pragma unroll
                    for (int o = 0; o < 4; o++) {
                        acck[o] += xv * swk[wbase + ci * 4 + o];
                        accv[o] += xv * swv[wbase + ci * 4 + o];
                    }
                }
            }
        }
        float msk = 0.f, msv = 0.f;
#pragma unroll
        for (int o = 0; o < 4; o++) { msk += acck[o] * acck[o]; msv += accv[o] * accv[o]; }
        float ik = rsqrtf(msk * 0.25f + 1e-6f);
        float iv = rsqrtf(msv * 0.25f + 1e-6f);
        int base = t * DM + (h * WW + w) * CC;
#pragma unroll
        for (int o = 0; o < 4; o++) {
            g_nk[base + o] = acck[o] * ik * ssk[o];
            g_nv[base + o] = accv[o] * iv * ssv[o];
        }
    } else {
        int i = (blockIdx.x - 1568) * 256 + tid;   // 65536 threads
        for (int k = i; k < DH * DM; k += 65536) g_W2[k] = W2[k];
        if (i < DM) g_b2[i] = b2[i];
    }
}

// ---------------- GEMM tile body (64m x 64n x 32k per iter, 128 thr, 8m x 4n/thread) ----------------
__device__ __forceinline__ void gemm64(
    const float* __restrict__ A, const float* __restrict__ B, float* __restrict__ Cseg,
    int mbase, int n0g, int k0, int kiter,
    int lda, int ldb, int ntot, int transb,
    float (&sA)[32][68], float (&sB)[32][68])
{
    int tid = threadIdx.x;
    int m0 = (tid >> 4) * 8;
    int n0 = (tid & 15) * 4;
    ull acc[4][4];
#pragma unroll
    for (int i = 0; i < 4; i++)
#pragma unroll
        for (int j = 0; j < 4; j++) acc[i][j] = 0ULL;

    for (int it = 0; it < kiter; it++) {
        int kk0 = k0 + it * 32;
        if (it) __syncthreads();
        // load A (64m x 32k) transposed -> sA[k][m]
#pragma unroll
        for (int i = tid; i < 512; i += 128) {
            int m = i >> 3;
            int f4 = (i & 7) * 4;
            float4 v = *reinterpret_cast<const float4*>(A + (size_t)(mbase + m) * lda + kk0 + f4);
            sA[f4][m] = v.x; sA[f4 + 1][m] = v.y; sA[f4 + 2][m] = v.z; sA[f4 + 3][m] = v.w;
        }
        if (!transb) {
#pragma unroll
            for (int i = tid; i < 512; i += 128) {
                int k = i >> 4;
                int n4 = (i & 15) * 4;
                *reinterpret_cast<float4*>(&sB[k][n4]) =
                    *reinterpret_cast<const float4*>(B + (size_t)(kk0 + k) * ldb + n0g + n4);
            }
        } else {
#pragma unroll
            for (int i = tid; i < 512; i += 128) {
                int n = i >> 3;
                int f4 = (i & 7) * 4;
                float4 v = *reinterpret_cast<const float4*>(B + (size_t)(n0g + n) * ldb + kk0 + f4);
                sB[f4][n] = v.x; sB[f4 + 1][n] = v.y; sB[f4 + 2][n] = v.z; sB[f4 + 3][n] = v.w;
            }
        }
        __syncthreads();
#pragma unroll
        for (int kk = 0; kk < 32; kk++) {
            ulonglong2 alo = *reinterpret_cast<const ulonglong2*>(&sA[kk][m0]);
            ulonglong2 ahi = *reinterpret_cast<const ulonglong2*>(&sA[kk][m0 + 4]);
            float4 b = *reinterpret_cast<const float4*>(&sB[kk][n0]);
            ull b0 = pk2(b.x, b.x), b1 = pk2(b.y, b.y), b2 = pk2(b.z, b.z), b3 = pk2(b.w, b.w);
            FFMA2(acc[0][0], alo.x, b0); FFMA2(acc[0][1], alo.x, b1);
            FFMA2(acc[0][2], alo.x, b2); FFMA2(acc[0][3], alo.x, b3);
            FFMA2(acc[1][0], alo.y, b0); FFMA2(acc[1][1], alo.y, b1);
            FFMA2(acc[1][2], alo.y, b2); FFMA2(acc[1][3], alo.y, b3);
            FFMA2(acc[2][0], ahi.x, b0); FFMA2(acc[2][1], ahi.x, b1);
            FFMA2(acc[2][2], ahi.x, b2); FFMA2(acc[2][3], ahi.x, b3);
            FFMA2(acc[3][0], ahi.y, b0); FFMA2(acc[3][1], ahi.y, b1);
            FFMA2(acc[3][2], ahi.y, b2); FFMA2(acc[3][3], ahi.y, b3);
        }
    }
    float* P = Cseg + (size_t)(mbase + m0) * ntot + n0g + n0;
#pragma unroll
    for (int mp = 0; mp < 4; mp++) {
        float e0, o0, e1, o1, e2, o2, e3, o3;
        upk2(e0, o0, acc[mp][0]); upk2(e1, o1, acc[mp][1]);
        upk2(e2, o2, acc[mp][2]); upk2(e3, o3, acc[mp][3]);
        *reinterpret_cast<float4*>(P + (size_t)(2 * mp) * ntot)     = make_float4(e0, e1, e2, e3);
        *reinterpret_cast<float4*>(P + (size_t)(2 * mp + 1) * ntot) = make_float4(o0, o1, o2, o3);
    }
}

// ---------------- H0 GEMM: H0_part = K(all 512) @ W1_0  (M=512, 14 segs of 224) ----------------
__global__ void __launch_bounds__(128) h0_gemm_kernel(const float* __restrict__ W1in) {
    __shared__ float sA[32][68];
    __shared__ float sB[32][68];
    int bx = blockIdx.x;          // 896 = 14seg x 8mt x 8nt
    int seg = bx >> 6;
    int r = bx & 63;
    int mbase = (r >> 3) * 64;
    int n0g = (r & 7) * 64;
    gemm64(g_nk, W1in, g_ppart + (size_t)seg * (T_TOK * DH),
           mbase, n0g, seg * 224, 7, DM, DH, DH, 0, sA, sB);
}

// ---------------- reduce H0 partials + b1 ----------------
__global__ void __launch_bounds__(256) reduceH0_kernel(const float* __restrict__ b1in) {
    int e = blockIdx.x * 256 + threadIdx.x;   // 1024 blocks = 262144
    float s = b1in[e & (DH - 1)];
#pragma unroll
    for (int sg = 0; sg < H0SEG; sg++) s += g_ppart[(size_t)sg * (T_TOK * DH) + e];
    g_H0[e] = s;
}

// ---------------- all-pairs Gram: G'[c][c'] = K_c K_{c'}^T + 1  (c' <= c) ----------------
__global__ void __launch_bounds__(256) gram_kernel() {
    int t = blockIdx.x * 256 + threadIdx.x;   // 576 blocks = 147456
    int p = t >> 12;                           // 0..35
    int o = t & 4095;
    int m = o >> 6;
    int n = o & 63;
    int c = 0, q = p;
    while (q > c) { q -= c + 1; c++; }
    int cp = q;
    const ull* pa = reinterpret_cast<const ull*>(g_nk + (size_t)(c * 64 + m) * DM);
    const ull* pb = reinterpret_cast<const ull*>(g_nk + (size_t)(cp * 64 + n) * DM);
    ull a0 = 0ULL, a1 = 0ULL, a2 = 0ULL, a3 = 0ULL;
#pragma unroll 4
    for (int k = 0; k < 1568; k += 4) {
        FFMA2(a0, pa[k], pb[k]);
        FFMA2(a1, pa[k + 1], pb[k + 1]);
        FFMA2(a2, pa[k + 2], pb[k + 2]);
        FFMA2(a3, pa[k + 3], pb[k + 3]);
    }
    float l0, h0, l1, h1, l2, h2, l3, h3;
    upk2(l0, h0, a0); upk2(l1, h1, a1); upk2(l2, h2, a2); upk2(l3, h3, a3);
    g_Gall[p * 4096 + o] = ((l0 + h0) + (l1 + h1)) + ((l2 + h2) + (l3 + h3)) + 1.0f;
}

// ---------------- hstage: A_c = gelu(H_c), A2_{c-1} = gelu(H2_{c-1}) via Gram corrections ----------------
// blocks [0,128): A_c (c<8); at c==8 skip. blocks [128,256): A2_{c-1} (c>0); at c==0 write zeros.
__global__ void __launch_bounds__(256) hstage_kernel(int c, float wgt) {
    int bx = blockIdx.x;
    int tid = threadIdx.x;
    if (bx < 128) {
        if (c >= NCHUNK) return;
        int e = bx * 256 + tid;   // 32768
        int m = e >> 9;
        int j = e & (DH - 1);
        float H;
        if (c == 0) {
            H = g_H0[e];
        } else {
            float s = 0.f;
            const float* Gb = g_Gall + (size_t)(c * (c + 1) / 2) * 4096 + m * 64;
            for (int cp = 0; cp < c; cp++) {
                const float* Gr = Gb + cp * 4096;
                const float* dhp = g_dhist + (size_t)cp * (CHUNK * DH) + j;
                float ss = 0.f;
#pragma unroll 8
                for (int mp = 0; mp < 64; mp++) ss += Gr[mp] * dhp[mp * DH];
                s += ss;
            }
            H = g_H0[(size_t)c * (CHUNK * DH) + e] - wgt * s;
        }
        g_Hbuf[c & 1][e] = H;
        g_A[e] = gelu_f(H);
    } else {
        int e = (bx - 128) * 256 + tid;
        if (c == 0) { g_A[CHUNK * DH + e] = 0.f; return; }
        int m = e >> 9;
        int j = e & (DH - 1);
        int cm = c - 1;                      // 0..7 (c in 1..8)
        const float* Gr = g_Gall + (size_t)(cm * (cm + 1) / 2 + cm) * 4096 + m * 64;
        const float* dhp = g_dhist + (size_t)cm * (CHUNK * DH) + j;
        float ss = 0.f;
#pragma unroll 8
        for (int mp = 0; mp < 64; mp++) ss += Gr[mp] * dhp[mp * DH];
        float H2 = g_Hbuf[cm & 1][e] - wgt * ss;
        g_A[CHUNK * DH + e] = gelu_f(H2);
    }
}

// ---------------- fused pred GEMM: [A_c ; A2_{c-1}] @ W2 -> ppart (M=128) ----------------
// mode 0: grid 1568 (both halves). mode 1 (epilogue): grid 784, rows 64-127 only.
__global__ void __launch_bounds__(128) predfused_kernel(int mode) {
    __shared__ float sA[32][68];
    __shared__ float sB[32][68];
    int bx = blockIdx.x;
    int seg, n0g, mbase;
    if (mode == 0) {
        seg = bx / 98;
        int r = bx % 98;
        mbase = (r & 1) * 64;
        n0g = (r >> 1) * 64;
    } else {
        seg = bx / 49;
        n0g = (bx % 49) * 64;
        mbase = 64;
    }
    gemm64(g_A, g_W2, g_ppart + (size_t)seg * (2 * CHUNK * DM),
           mbase, n0g, seg * 32, 1, DH, DM, DM, 0, sA, sB);
}

// ---------------- reduce pred partials: rows 0-63 -> dpred_c, rows 64-127 -> out_{c-1} ----------------
__global__ void __launch_bounds__(256) reduce2both_kernel(int c, float* __restrict__ out) {
    int f = blockIdx.x * 256 + threadIdx.x;    // 392 blocks = 100352
    int idx4 = f * 4;                           // over [128][3136]
    int m = idx4 / DM;
    int d = idx4 % DM;
    ulonglong2 s = *reinterpret_cast<const ulonglong2*>(&g_b2[d]);
#pragma unroll
    for (int sg = 0; sg < PSEG; sg++) {
        ulonglong2 p = *reinterpret_cast<const ulonglong2*>(&g_ppart[(size_t)sg * (2 * CHUNK * DM) + idx4]);
        ADDX2(s.x, p.x);
        ADDX2(s.y, p.y);
    }
    float s0, s1, s2, s3;
    upk2(s0, s1, s.x); upk2(s2, s3, s.y);
    if (m < CHUNK) {
        if (c < NCHUNK) {
            float4 v = *reinterpret_cast<const float4*>(&g_nv[(size_t)c * (CHUNK * DM) + idx4]);
            *reinterpret_cast<float4*>(&g_dpred[idx4]) =
                make_float4(2.f * (s0 - v.x), 2.f * (s1 - v.y), 2.f * (s2 - v.z), 2.f * (s3 - v.w));
        }
    } else {
        if (c > 0) {
            *reinterpret_cast<float4*>(&out[(size_t)(c - 1) * (CHUNK * DM) + (idx4 - CHUNK * DM)]) =
                make_float4(s0, s1, s2, s3);
        }
    }
}

// ---------------- dadh GEMM: dpred@W2^T -> fpart ----------------
__global__ void __launch_bounds__(128) dadh_gemm_kernel() {
    __shared__ float sA[32][68];
    __shared__ float sB[32][68];
    int bx = blockIdx.x;            // 784 = 98seg x 8nt
    int nt = bx & 7;
    int seg = bx >> 3;
    gemm64(g_dpred, g_W2, g_fpart + (size_t)seg * (CHUNK * DH),
           0, nt * 64, seg * 32, 1, DM, DM, DH, 1, sA, sB);
}

// ---------------- reduce dadh partials -> dhist[c] (4-way sliced, with dgelu) ----------------
__global__ void __launch_bounds__(256) reduceDh_kernel(int c) {
    __shared__ float red[256];
    int tid = threadIdx.x;
    int slice = tid >> 6;
    int o = tid & 63;
    int idx = blockIdx.x * 64 + o;     // 512 blocks -> 32768 outputs
    const int start[4] = {0, 25, 50, 74};
    const int cnt[4] = {25, 25, 24, 24};
    float s = 0.f;
    int s0 = start[slice], n = cnt[slice];
    const float* P = g_fpart + idx;
#pragma unroll 5
    for (int sg = 0; sg < n; sg++)
        s += P[(size_t)(s0 + sg) * (CHUNK * DH)];
    red[tid] = s;
    __syncthreads();
    if (slice == 0) {
        float t = red[o] + red[64 + o] + red[128 + o] + red[192 + o];
        g_dhist[(size_t)c * (CHUNK * DH) + idx] = t * dgelu_f(g_Hbuf[c & 1][idx]);
    }
}

// ---------------- updW2: W2 -= w * A_c^T @ dpred ; b2 -= w * colsum(dpred) ----------------
__global__ void __launch_bounds__(128) updW2_kernel(float wgt) {
    int tid = threadIdx.x;
    int bx = blockIdx.x;
    if (bx < 392) {
        __shared__ float sU[64][68];
        __shared__ float sV[64][68];
        int jt = bx / 49, dt = bx % 49;
        int r0 = jt * 64, c0 = dt * 64;
#pragma unroll
        for (int i = tid; i < 1024; i += 128) {
            int m = i >> 4;
            int r4 = (i & 15) * 4;
            *reinterpret_cast<float4*>(&sU[m][r4]) =
                *reinterpret_cast<const float4*>(g_A + (size_t)m * DH + r0 + r4);
            *reinterpret_cast<float4*>(&sV[m][r4]) =
                *reinterpret_cast<const float4*>(g_dpred + (size_t)m * DM + c0 + r4);
        }
        __syncthreads();
        int rt = (tid >> 4) * 8;
        int ct = (tid & 15) * 4;
        ull acc[4][4];
#pragma unroll
        for (int i = 0; i < 4; i++)
#pragma unroll
            for (int j = 0; j < 4; j++) acc[i][j] = 0ULL;
#pragma unroll 8
        for (int m = 0; m < 64; m++) {
            ulonglong2 alo = *reinterpret_cast<const ulonglong2*>(&sU[m][rt]);
            ulonglong2 ahi = *reinterpret_cast<const ulonglong2*>(&sU[m][rt + 4]);
            float4 b = *reinterpret_cast<const float4*>(&sV[m][ct]);
            ull b0 = pk2(b.x, b.x), b1 = pk2(b.y, b.y), b2 = pk2(b.z, b.z), b3 = pk2(b.w, b.w);
            FFMA2(acc[0][0], alo.x, b0); FFMA2(acc[0][1], alo.x, b1);
            FFMA2(acc[0][2], alo.x, b2); FFMA2(acc[0][3], alo.x, b3);
            FFMA2(acc[1][0], alo.y, b0); FFMA2(acc[1][1], alo.y, b1);
            FFMA2(acc[1][2], alo.y, b2); FFMA2(acc[1][3], alo.y, b3);
            FFMA2(acc[2][0], ahi.x, b0); FFMA2(acc[2][1], ahi.x, b1);
            FFMA2(acc[2][2], ahi.x, b2); FFMA2(acc[2][3], ahi.x, b3);
            FFMA2(acc[3][0], ahi.y, b0); FFMA2(acc[3][1], ahi.y, b1);
            FFMA2(acc[3][2], ahi.y, b2); FFMA2(acc[3][3], ahi.y, b3);
        }
#pragma unroll
        for (int mp = 0; mp < 4; mp++) {
            float e0, o0, e1, o1, e2, o2, e3, o3;
            upk2(e0, o0, acc[mp][0]); upk2(e1, o1, acc[mp][1]);
            upk2(e2, o2, acc[mp][2]); upk2(e3, o3, acc[mp][3]);
            float* We = g_W2 + (size_t)(r0 + rt + 2 * mp) * DM + c0 + ct;
            float4 olde = *reinterpret_cast<float4*>(We);
            olde.x -= wgt * e0; olde.y -= wgt * e1; olde.z -= wgt * e2; olde.w -= wgt * e3;
            *reinterpret_cast<float4*>(We) = olde;
            float* Wo = g_W2 + (size_t)(r0 + rt + 2 * mp + 1) * DM + c0 + ct;
            float4 oldo = *reinterpret_cast<float4*>(Wo);
            oldo.x -= wgt * o0; oldo.y -= wgt * o1; oldo.z -= wgt * o2; oldo.w -= wgt * o3;
            *reinterpret_cast<float4*>(Wo) = oldo;
        }
    } else {
        int i = (bx - 392) * 128 + tid;   // 3200 >= 3136
        if (i < DM) {
            float s = 0.f;
#pragma unroll 8
            for (int m = 0; m < CHUNK; m++) s += g_dpred[(size_t)m * DM + i];
            g_b2[i] -= wgt * s;
        }
    }
}

// ---------------- launch ----------------
extern "C" void kernel_launch(void* const* d_in, const int* in_sizes, int n_in,
                              void* d_out, int out_size) {
    const float* x   = (const float*)d_in[0];
    const float* ckw = (const float*)d_in[1];
    const float* ckb = (const float*)d_in[2];
    const float* cvw = (const float*)d_in[3];
    const float* cvb = (const float*)d_in[4];
    const float* rsk = (const float*)d_in[5];
    const float* rsv = (const float*)d_in[6];
    const float* W1  = (const float*)d_in[7];
    const float* b1  = (const float*)d_in[8];
    const float* W2  = (const float*)d_in[9];
    const float* b2  = (const float*)d_in[10];
    float* out = (float*)d_out;

    // weights[i] = eta0*alpha^i * alpha^(CHUNK-1)/alpha^i = const
    float wgt = (float)(0.1 * pow(0.9, 63.0));

    prologue_kernel<<<1824, 256>>>(x, ckw, ckb, cvw, cvb, rsk, rsv, W2, b2);
    h0_gemm_kernel<<<896, 128>>>(W1);
    gram_kernel<<<576, 256>>>();
    reduceH0_kernel<<<1024, 256>>>(b1);

    for (int c = 0; c < NCHUNK; c++) {
        hstage_kernel<<<256, 256>>>(c, wgt);
        predfused_kernel<<<1568, 128>>>(0);
        reduce2both_kernel<<<392, 256>>>(c, out);
        dadh_gemm_kernel<<<784, 128>>>();
        reduceDh_kernel<<<512, 256>>>(c);
        updW2_kernel<<<417, 128>>>(wgt);
    }
    // epilogue: A2_7 -> recall pred -> out chunk 7
    hstage_kernel<<<256, 256>>>(NCHUNK, wgt);
    predfused_kernel<<<784, 128>>>(1);
    reduce2both_kernel<<<392, 256>>>(NCHUNK, out);
}